// round 14
// baseline (speedup 1.0000x reference)
#include <cuda_runtime.h>
#include <cuda_bf16.h>
#include <math.h>
#include <cstdint>

// Problem constants
#define BB   32
#define TT   4096
#define DZC  128
#define NDC  32
#define DHC  128
#define GG   384            // 3*DZ
#define IND  192            // 2*ND + DH

#define TBLK      128                 // timesteps per GEMM tile
#define NTBLK     (TT / TBLK)         // 32 t-blocks per batch
#define GEMM_CTAS (NTBLK * BB * 3)    // 3072
#define SCAN_CTAS (2 * BB)            // 64: cluster pair per batch

// ---------------- scratch (no cudaMalloc allowed) ----------------
__device__ float        g_gi[(size_t)BB * TT * GG + 2 * GG];
__device__ unsigned int g_cnt[BB * NTBLK];

// ---------------- packed fp32x2 helpers (sm_100+) ----------------
__device__ __forceinline__ void fma2(unsigned long long& d,
                                     unsigned long long a,
                                     unsigned long long b) {
    asm("fma.rn.f32x2 %0, %1, %2, %0;" : "+l"(d) : "l"(a), "l"(b));
}
__device__ __forceinline__ void add2(unsigned long long& d, unsigned long long a) {
    asm("add.rn.f32x2 %0, %0, %1;" : "+l"(d) : "l"(a));
}
__device__ __forceinline__ unsigned long long dup2(float a) {
    unsigned long long r;
    asm("mov.b64 %0, {%1, %1};" : "=l"(r) : "f"(a));
    return r;
}
__device__ __forceinline__ unsigned long long pack2(float x, float y) {
    unsigned long long r;
    asm("mov.b64 %0, {%1, %2};" : "=l"(r) : "f"(x), "f"(y));
    return r;
}
__device__ __forceinline__ void unpk(unsigned long long v, float& x, float& y) {
    asm("mov.b64 {%0, %1}, %2;" : "=f"(x), "=f"(y) : "l"(v));
}
__device__ __forceinline__ float ex2f_(float x) {
    float y; asm("ex2.approx.f32 %0, %1;" : "=f"(y) : "f"(x)); return y;
}
__device__ __forceinline__ float tanhap_(float x) {
    float y; asm("tanh.approx.f32 %0, %1;" : "=f"(y) : "f"(x)); return y;
}
__device__ __forceinline__ unsigned int ldvol_(const unsigned int* p) {
    unsigned int v;
    asm volatile("ld.volatile.global.b32 %0, [%1];" : "=r"(v) : "l"(p));
    return v;
}
__device__ __forceinline__ uint32_t smem2u32_(const void* p) {
    uint32_t a;
    asm("{ .reg .u64 t; cvta.to.shared.u64 t, %1; cvt.u32.u64 %0, t; }"
        : "=r"(a) : "l"(p));
    return a;
}
__device__ __forceinline__ uint32_t mapa_(uint32_t addr, uint32_t rank) {
    uint32_t r;
    asm("mapa.shared::cluster.u32 %0, %1, %2;" : "=r"(r) : "r"(addr), "r"(rank));
    return r;
}
__device__ __forceinline__ void waitbar_(uint32_t mbar, uint32_t parity) {
    uint32_t done;
    asm volatile(
        "{\n\t.reg .pred p;\n\t"
        "mbarrier.try_wait.parity.acquire.cluster.shared::cta.b64 p, [%1], %2;\n\t"
        "selp.b32 %0, 1, 0, p;\n\t}"
        : "=r"(done) : "r"(mbar), "r"(parity) : "memory");
    while (!done) {
        asm volatile(
            "{\n\t.reg .pred p;\n\t"
            "mbarrier.try_wait.parity.acquire.cluster.shared::cta.b64 p, [%1], %2, 0x989680;\n\t"
            "selp.b32 %0, 1, 0, p;\n\t}"
            : "=r"(done) : "r"(mbar), "r"(parity) : "memory");
    }
}

// =====================================================================
// Fused kernel, cluster dims (2,1,1).
//   blockIdx.x < 64  -> scan role: cluster pair per batch, K split 2 ways
//   blockIdx.x >= 64 -> GEMM tile role (clusters inert)
// GEMM adds b_ih; folds b_hh for r/u rows; r,u rows prescaled 0.5
// (gate = 0.5 + 0.5*tanh(0.5*x)).
// =====================================================================
#define Bb 128
#define BN 128
#define BK 16

struct ScanSmem {
    float dtbuf[TT + 4];
    float zbA[80];                 // my K-slice of z_d, halves 192B apart
    float zbB[80];
    float partA[DZC * 4];          // peer-written partials {Sr,Su,Sn,pad}
    float partB[DZC * 4];
    unsigned long long bars[2];    // mbarriers (A,B)
};
struct GemmSmem {
    float As[2][BK][Bb];
    float Bs[2][BK][BN];
};

__global__ __launch_bounds__(256, 1) __cluster_dims__(2, 1, 1)
void fused_kernel(
    const float* __restrict__ z0, const float* __restrict__ t_dyn,
    const int* __restrict__ dyn_lens,
    const float* __restrict__ Y, const float* __restrict__ M,
    const float* __restrict__ H,
    const float* __restrict__ W_ih, const float* __restrict__ b_ih,
    const float* __restrict__ W_hh, const float* __restrict__ b_hh,
    const float* __restrict__ log_gamma,
    float* __restrict__ z_final, float* __restrict__ Z_traj)
{
    __shared__ __align__(16) union { ScanSmem scan; GemmSmem gemm; } sm;

    const int tid = threadIdx.x;

    if (blockIdx.x >= SCAN_CTAS) {
        // ================= GEMM role =================
        const int gidx = blockIdx.x - SCAN_CTAS;
        const int tb   = gidx / (BB * 3);
        const int rem  = gidx % (BB * 3);
        const int b    = rem / 3;
        const int gblk = rem % 3;
        const int bt0  = b * TT + tb * TBLK;
        const int g0   = gblk * BN;
        const float wscale = (gblk < 2) ? 0.5f : 1.0f;

        float* gi = g_gi;
        const int tx = tid & 15;
        const int ty = tid >> 4;

        unsigned long long acc[8][4];
        #pragma unroll
        for (int i = 0; i < 8; i++)
            #pragma unroll
            for (int j = 0; j < 4; j++) acc[i][j] = 0ull;

        auto loadA = [&](int stage, int kc) {
            #pragma unroll
            for (int i = 0; i < 2; i++) {
                int e  = tid + 256 * i;
                int m  = e & 127;
                int k4 = e >> 7;
                int kk = kc * BK + k4 * 4;
                int bt = bt0 + m;
                float4 v;
                if (kk < 32)       v = *(const float4*)(Y + (size_t)bt * NDC + kk);
                else if (kk < 64)  v = *(const float4*)(M + (size_t)bt * NDC + (kk - 32));
                else               v = *(const float4*)(H + (size_t)bt * DHC + (kk - 64));
                sm.gemm.As[stage][k4 * 4 + 0][m] = v.x;
                sm.gemm.As[stage][k4 * 4 + 1][m] = v.y;
                sm.gemm.As[stage][k4 * 4 + 2][m] = v.z;
                sm.gemm.As[stage][k4 * 4 + 3][m] = v.w;
            }
        };
        auto loadB = [&](int stage, int kc) {
            #pragma unroll
            for (int i = 0; i < 2; i++) {
                int e  = tid + 256 * i;
                int g  = e & 127;
                int k4 = e >> 7;
                int kk = kc * BK + k4 * 4;
                float4 v = *(const float4*)(W_ih + (size_t)(g0 + g) * IND + kk);
                sm.gemm.Bs[stage][k4 * 4 + 0][g] = v.x * wscale;
                sm.gemm.Bs[stage][k4 * 4 + 1][g] = v.y * wscale;
                sm.gemm.Bs[stage][k4 * 4 + 2][g] = v.z * wscale;
                sm.gemm.Bs[stage][k4 * 4 + 3][g] = v.w * wscale;
            }
        };

        loadA(0, 0); loadB(0, 0);
        __syncthreads();

        const int NKC = IND / BK;   // 12
        for (int kc = 0; kc < NKC; kc++) {
            int cur = kc & 1, nxt = cur ^ 1;
            if (kc + 1 < NKC) { loadA(nxt, kc + 1); loadB(nxt, kc + 1); }
            #pragma unroll
            for (int k = 0; k < BK; k++) {
                float a[8];
                *(float4*)&a[0] = *(const float4*)&sm.gemm.As[cur][k][ty * 8];
                *(float4*)&a[4] = *(const float4*)&sm.gemm.As[cur][k][ty * 8 + 4];
                unsigned long long bv[4];
                {
                    ulonglong2 b0 = *(const ulonglong2*)&sm.gemm.Bs[cur][k][tx * 8];
                    ulonglong2 b1 = *(const ulonglong2*)&sm.gemm.Bs[cur][k][tx * 8 + 4];
                    bv[0] = b0.x; bv[1] = b0.y; bv[2] = b1.x; bv[3] = b1.y;
                }
                #pragma unroll
                for (int i = 0; i < 8; i++) {
                    unsigned long long ad = dup2(a[i]);
                    fma2(acc[i][0], ad, bv[0]);
                    fma2(acc[i][1], ad, bv[1]);
                    fma2(acc[i][2], ad, bv[2]);
                    fma2(acc[i][3], ad, bv[3]);
                }
            }
            __syncthreads();
        }

        float bia[8];
        *(float4*)&bia[0] = *(const float4*)(b_ih + g0 + tx * 8);
        *(float4*)&bia[4] = *(const float4*)(b_ih + g0 + tx * 8 + 4);
        if (gblk < 2) {
            float bh[8];
            *(float4*)&bh[0] = *(const float4*)(b_hh + g0 + tx * 8);
            *(float4*)&bh[4] = *(const float4*)(b_hh + g0 + tx * 8 + 4);
            #pragma unroll
            for (int j = 0; j < 8; j++) bia[j] = (bia[j] + bh[j]) * 0.5f;
        }

        #pragma unroll
        for (int i = 0; i < 8; i++) {
            float c[8];
            unpk(acc[i][0], c[0], c[1]);
            unpk(acc[i][1], c[2], c[3]);
            unpk(acc[i][2], c[4], c[5]);
            unpk(acc[i][3], c[6], c[7]);
            #pragma unroll
            for (int j = 0; j < 8; j++) c[j] += bia[j];
            int bt = bt0 + ty * 8 + i;
            float* outp = gi + (size_t)bt * GG + g0 + tx * 8;
            *(float4*)(outp)     = *(float4*)&c[0];
            *(float4*)(outp + 4) = *(float4*)&c[4];
        }

        __threadfence();
        __syncthreads();
        if (tid == 0) atomicAdd(&g_cnt[b * NTBLK + tb], 1u);
        return;
    }

    // ================= scan role: cluster pair per batch =================
    const int b     = blockIdx.x >> 1;
    const int crank = blockIdx.x & 1;    // cluster rank = K-half owner
    const int j     = tid >> 1;          // state dim 0..127
    const int q     = tid & 1;           // K-quarter within my half

    float* dtbuf = sm.scan.dtbuf;
    float* zbA   = sm.scan.zbA;
    float* zbB   = sm.scan.zbB;
    float* partA = sm.scan.partA;
    float* partB = sm.scan.partB;

    // dt table
    {
        const float* tp = t_dyn + (size_t)b * TT;
        for (int i = tid; i < TT; i += 256) {
            float cur = __ldg(tp + i);
            float prv = (i > 0) ? __ldg(tp + i - 1) : cur;
            dtbuf[i] = fmaxf(cur - prv, 0.0f);
        }
        if (tid == 0) dtbuf[TT] = 0.0f;
    }

    // mbarriers: arrivals come from the PEER's 128 q==0 threads
    const uint32_t barA_loc = smem2u32_(&sm.scan.bars[0]);
    const uint32_t barB_loc = smem2u32_(&sm.scan.bars[1]);
    if (tid == 0) {
        asm volatile("mbarrier.init.shared.b64 [%0], %1;" :: "r"(barA_loc), "r"(128u) : "memory");
        asm volatile("mbarrier.init.shared.b64 [%0], %1;" :: "r"(barB_loc), "r"(128u) : "memory");
    }

    const uint32_t peer = (uint32_t)(crank ^ 1);
    const uint32_t barA_rem  = mapa_(barA_loc, peer);
    const uint32_t barB_rem  = mapa_(barB_loc, peer);
    const uint32_t partA_rem = mapa_(smem2u32_(partA), peer);
    const uint32_t partB_rem = mapa_(smem2u32_(partB), peer);

    // weights: rows {j,128+j,256+j}, K slice [64*crank+32*q, +32) -> 48 u64
    const int k0 = 64 * crank + 32 * q;
    unsigned long long Wr[16], Wu[16], Wn[16];
    {
        const float4* wr = (const float4*)(W_hh + (size_t)j * DZC + k0);
        const float4* wu = (const float4*)(W_hh + (size_t)(128 + j) * DZC + k0);
        const float4* wn = (const float4*)(W_hh + (size_t)(256 + j) * DZC + k0);
        #pragma unroll
        for (int i = 0; i < 8; i++) {
            float4 a = wr[i];
            Wr[2*i]   = pack2(a.x * 0.5f, a.y * 0.5f);   // r prescale 0.5
            Wr[2*i+1] = pack2(a.z * 0.5f, a.w * 0.5f);
            float4 c = wu[i];
            Wu[2*i]   = pack2(c.x * 0.5f, c.y * 0.5f);   // u prescale 0.5
            Wu[2*i+1] = pack2(c.z * 0.5f, c.w * 0.5f);
            float4 d = wn[i];
            Wn[2*i]   = pack2(d.x, d.y);
            Wn[2*i+1] = pack2(d.z, d.w);
        }
    }
    const float bh_n = (crank == 0 && q == 0) ? b_hh[256 + j] : 0.0f;
    const int   L    = dyn_lens[b];

    float lg  = log_gamma[j];
    float sp  = (lg > 20.0f) ? lg : log1pf(expf(lg));
    const float gje = -1.4426950408889634f * sp;

    const unsigned int* cntp = &g_cnt[b * NTBLK];

    // my z-slice write index: s = j-64*crank in [0,64); halves 192B apart
    const bool zown = ((j >> 6) == crank);
    const int  s    = j & 63;
    const int  zidx = s + ((s >> 5) << 4);

    __syncthreads();            // dtbuf + mbarrier init local-visible
    asm volatile("barrier.cluster.arrive.aligned;" ::: "memory");
    asm volatile("barrier.cluster.wait.aligned;"   ::: "memory");   // init visible to peer

    while (ldvol_(cntp) < 3u) { }
    __threadfence();

    // gi streams, distance-1 prefetch (only crank0 injects r/u gi)
    const float* pG = g_gi + (size_t)b * TT * GG + q * DZC + j;
    const float* pN = g_gi + (size_t)b * TT * GG + 2 * DZC + j;
    float gi_c = __ldg(pG);
    float gn_c = __ldg(pN);
    pG += GG; pN += GG;

    float* zp = Z_traj + (size_t)b * TT * DZC + j;

    float zdj = z0[(size_t)b * DZC + j];
    float zlast = zdj;
    if (q == 0 && zown) zbA[zidx] = zdj;

    int phA = 0, phB = 0;

    auto step = [&](int tn, int offG, int offZ, bool chk,
                    const float* __restrict__ zr, float* __restrict__ zw,
                    const float* __restrict__ partRd, uint32_t partWr_rem,
                    uint32_t barLoc, uint32_t barRem, int& ph) {
        __syncthreads();   // local z slice + part consumption ordered

        if (chk && (tn & (TBLK - 1)) == 0 && tn < L) {
            unsigned int need = (unsigned)(tn >> 7);
            while (ldvol_(cntp + need) < 3u) { }
            __threadfence();
        }
        float giN = __ldg(pG + offG), gnN = __ldg(pN + offG);

        float edn = ex2f_(gje * dtbuf[tn]);

        // dot over my 32-K slice: 8 LDS.128, 48 fma2
        const ulonglong2* zc = (const ulonglong2*)(zr + (q ? 48 : 0));
        unsigned long long ar0 = 0, ar1 = 0, au0 = 0, au1 = 0, an0 = 0, an1 = 0;
        #pragma unroll
        for (int i = 0; i < 8; i += 2) {
            ulonglong2 v0 = zc[i];
            ulonglong2 v1 = zc[i + 1];
            fma2(ar0, Wr[2*i],   v0.x); fma2(ar0, Wr[2*i+1], v0.y);
            fma2(au0, Wu[2*i],   v0.x); fma2(au0, Wu[2*i+1], v0.y);
            fma2(an0, Wn[2*i],   v0.x); fma2(an0, Wn[2*i+1], v0.y);
            fma2(ar1, Wr[2*i+2], v1.x); fma2(ar1, Wr[2*i+3], v1.y);
            fma2(au1, Wu[2*i+2], v1.x); fma2(au1, Wu[2*i+3], v1.y);
            fma2(an1, Wn[2*i+2], v1.x); fma2(an1, Wn[2*i+3], v1.y);
        }
        add2(ar0, ar1); add2(au0, au1); add2(an0, an1);
        float x, y;
        unpk(ar0, x, y); float Sr = x + y;
        unpk(au0, x, y); float Su = x + y;
        unpk(an0, x, y); float Sn = x + y;

        // gi (r/u prescaled 0.5 in GEMM) injected once, by crank0
        if (crank == 0) {
            if (q == 0) { Sr += gi_c; Sn += bh_n; }
            else        { Su += gi_c; }
        }
        // reduce q-pair -> my CTA's K-half partials (both lanes hold them)
        Sr += __shfl_xor_sync(0xffffffffu, Sr, 1);
        Su += __shfl_xor_sync(0xffffffffu, Su, 1);
        Sn += __shfl_xor_sync(0xffffffffu, Sn, 1);

        // ship partials to peer + arrive on peer's barrier
        if (q == 0) {
            uint32_t dst = partWr_rem + 16u * (uint32_t)j;
            unsigned long long d2 = pack2(Sr, Su);
            asm volatile("st.shared::cluster.b64 [%0], %1;" :: "r"(dst), "l"(d2) : "memory");
            asm volatile("st.shared::cluster.b32 [%0], %1;"
                         :: "r"(dst + 8u), "r"(__float_as_uint(Sn)) : "memory");
            asm volatile("mbarrier.arrive.release.cluster.shared::cluster.b64 _, [%0];"
                         :: "r"(barRem) : "memory");
        }
        // wait for peer's partials on my local barrier
        waitbar_(barLoc, (uint32_t)(ph & 1));
        ph++;

        float2 pp = *(const float2*)(partRd + 4 * j);
        float  pn = partRd[4 * j + 2];
        float SrT = Sr + pp.x;
        float SuT = Su + pp.y;
        float SnT = Sn + pn;

        float rr = fmaf(tanhap_(SrT), 0.5f, 0.5f);
        float uu = fmaf(tanhap_(SuT), 0.5f, 0.5f);
        float nn = tanhap_(fmaf(rr, SnT, gn_c));
        float znew = nn + uu * (zdj - nn);
        float zd   = znew * edn;
        if (q == 0) {
            if (zown) zw[zidx] = zd;
            if (crank == 0) *(zp + offZ) = znew;
        }
        zdj   = zd;
        zlast = znew;

        gi_c = giN; gn_c = gnN;
    };

    int t = 0;
    while (t + 2 <= L) {
        step(t + 1, 0,  0,   false, zbA, zbB, partA, partA_rem, barA_loc, barA_rem, phA);
        step(t + 2, GG, DZC, true,  zbB, zbA, partB, partB_rem, barB_loc, barB_rem, phB);
        pG += 2 * GG; pN += 2 * GG; zp += 2 * DZC;
        t += 2;
    }
    if (t < L) {
        step(t + 1, 0, 0, false, zbA, zbB, partA, partA_rem, barA_loc, barA_rem, phA);
        t += 1;
    }

    // closed-form inactive tail, 4-way split across (crank, q)
    {
        const float* tsrc = t_dyn + (size_t)b * TT;
        float tl = __ldg(tsrc + (L - 1));
        float zl = zlast;
        if (crank == 0 && q == 0) {
            float tend = __ldg(tsrc + (TT - 1));
            z_final[(size_t)b * DZC + j] = zl * ex2f_(gje * (tend - tl));
        }
        float* zob = Z_traj + (size_t)b * TT * DZC + j;
        for (int k = L + 2 * crank + q; k < TT; k += 4) {
            float v = zl * ex2f_(gje * (__ldg(tsrc + k) - tl));
            zob[(size_t)k * DZC] = v;
        }
    }

    // no CTA may exit while peer DSMEM traffic could be in flight
    asm volatile("barrier.cluster.arrive.aligned;" ::: "memory");
    asm volatile("barrier.cluster.wait.aligned;"   ::: "memory");
}

// =====================================================================
// launch
// =====================================================================
extern "C" void kernel_launch(void* const* d_in, const int* in_sizes, int n_in,
                              void* d_out, int out_size)
{
    const float* z0        = (const float*)d_in[0];
    const float* t_dyn     = (const float*)d_in[1];
    const float* Y         = (const float*)d_in[2];
    const float* M         = (const float*)d_in[3];
    const int*   dyn_lens  = (const int*)  d_in[4];
    const float* H         = (const float*)d_in[5];
    const float* W_ih      = (const float*)d_in[6];
    const float* b_ih      = (const float*)d_in[7];
    const float* W_hh      = (const float*)d_in[8];
    const float* b_hh      = (const float*)d_in[9];
    const float* log_gamma = (const float*)d_in[10];

    float* out     = (float*)d_out;
    float* z_final = out;                       // (B, DZ)
    float* Z_traj  = out + (size_t)BB * DZC;    // (B, T, DZ)

    void* cnt_ptr = nullptr;
    cudaGetSymbolAddress(&cnt_ptr, g_cnt);
    cudaMemsetAsync(cnt_ptr, 0, sizeof(unsigned int) * BB * NTBLK);

    fused_kernel<<<SCAN_CTAS + GEMM_CTAS, 256>>>(
        z0, t_dyn, dyn_lens, Y, M, H, W_ih, b_ih, W_hh, b_hh, log_gamma,
        z_final, Z_traj);
}

// round 15
// speedup vs baseline: 2.1779x; 2.1779x over previous
#include <cuda_runtime.h>
#include <cuda_bf16.h>
#include <math.h>
#include <cstdint>

// Problem constants
#define BB   32
#define TT   4096
#define DZC  128
#define NDC  32
#define DHC  128
#define GG   384            // 3*DZ
#define IND  192            // 2*ND + DH

#define TBLK      128                 // timesteps per GEMM tile
#define NTBLK     (TT / TBLK)         // 32 t-blocks per batch
#define GEMM_CTAS (NTBLK * BB * 3)    // 3072
#define SCAN_CTAS BB                  // 32

// z exchange buffer: halves padded 16 floats apart -> bank-disjoint reads
#define ZPAD 144

// ---------------- scratch (no cudaMalloc allowed) ----------------
__device__ float        g_gi[(size_t)BB * TT * GG + 2 * GG];
__device__ unsigned int g_cnt[BB * NTBLK];

// ---------------- packed fp32x2 helpers (sm_100+) ----------------
__device__ __forceinline__ void fma2(unsigned long long& d,
                                     unsigned long long a,
                                     unsigned long long b) {
    asm("fma.rn.f32x2 %0, %1, %2, %0;" : "+l"(d) : "l"(a), "l"(b));
}
__device__ __forceinline__ void add2(unsigned long long& d, unsigned long long a) {
    asm("add.rn.f32x2 %0, %0, %1;" : "+l"(d) : "l"(a));
}
__device__ __forceinline__ unsigned long long dup2(float a) {
    unsigned long long r;
    asm("mov.b64 %0, {%1, %1};" : "=l"(r) : "f"(a));
    return r;
}
__device__ __forceinline__ unsigned long long pack2(float x, float y) {
    unsigned long long r;
    asm("mov.b64 %0, {%1, %2};" : "=l"(r) : "f"(x), "f"(y));
    return r;
}
__device__ __forceinline__ void unpk(unsigned long long v, float& x, float& y) {
    asm("mov.b64 {%0, %1}, %2;" : "=f"(x), "=f"(y) : "l"(v));
}
__device__ __forceinline__ float ex2f_(float x) {
    float y; asm("ex2.approx.f32 %0, %1;" : "=f"(y) : "f"(x)); return y;
}
__device__ __forceinline__ float tanhap_(float x) {
    float y; asm("tanh.approx.f32 %0, %1;" : "=f"(y) : "f"(x)); return y;
}
__device__ __forceinline__ unsigned int ldvol_(const unsigned int* p) {
    unsigned int v;
    asm volatile("ld.volatile.global.b32 %0, [%1];" : "=r"(v) : "l"(p));
    return v;
}

// =====================================================================
// Fused kernel. blockIdx.x < 32  -> scan role (one CTA per batch)
//               blockIdx.x >= 32 -> GEMM tile role (t-block-major order)
// GEMM adds b_ih; folds b_hh for r/u rows; r,u rows prescaled 0.5
// (gate = 0.5 + 0.5*tanh(0.5*x)).
// =====================================================================
#define Bb 128
#define BN 128
#define BK 16

struct ScanSmem {
    float dtbuf[TT + 4];
    float zbA[ZPAD];
    float zbB[ZPAD];
};
struct GemmSmem {
    float As[2][BK][Bb];
    float Bs[2][BK][BN];
};

__global__ __launch_bounds__(256, 1) void fused_kernel(
    const float* __restrict__ z0, const float* __restrict__ t_dyn,
    const int* __restrict__ dyn_lens,
    const float* __restrict__ Y, const float* __restrict__ M,
    const float* __restrict__ H,
    const float* __restrict__ W_ih, const float* __restrict__ b_ih,
    const float* __restrict__ W_hh, const float* __restrict__ b_hh,
    const float* __restrict__ log_gamma,
    float* __restrict__ z_final, float* __restrict__ Z_traj)
{
    __shared__ __align__(16) union { ScanSmem scan; GemmSmem gemm; } sm;

    const int tid = threadIdx.x;

    if (blockIdx.x >= SCAN_CTAS) {
        // ================= GEMM role =================
        const int gidx = blockIdx.x - SCAN_CTAS;
        const int tb   = gidx / (BB * 3);
        const int rem  = gidx % (BB * 3);
        const int b    = rem / 3;
        const int gblk = rem % 3;
        const int bt0  = b * TT + tb * TBLK;
        const int g0   = gblk * BN;
        const float wscale = (gblk < 2) ? 0.5f : 1.0f;

        float* gi = g_gi;
        const int tx = tid & 15;
        const int ty = tid >> 4;

        unsigned long long acc[8][4];
        #pragma unroll
        for (int i = 0; i < 8; i++)
            #pragma unroll
            for (int j = 0; j < 4; j++) acc[i][j] = 0ull;

        auto loadA = [&](int stage, int kc) {
            #pragma unroll
            for (int i = 0; i < 2; i++) {
                int e  = tid + 256 * i;
                int m  = e & 127;
                int k4 = e >> 7;
                int kk = kc * BK + k4 * 4;
                int bt = bt0 + m;
                float4 v;
                if (kk < 32)       v = *(const float4*)(Y + (size_t)bt * NDC + kk);
                else if (kk < 64)  v = *(const float4*)(M + (size_t)bt * NDC + (kk - 32));
                else               v = *(const float4*)(H + (size_t)bt * DHC + (kk - 64));
                sm.gemm.As[stage][k4 * 4 + 0][m] = v.x;
                sm.gemm.As[stage][k4 * 4 + 1][m] = v.y;
                sm.gemm.As[stage][k4 * 4 + 2][m] = v.z;
                sm.gemm.As[stage][k4 * 4 + 3][m] = v.w;
            }
        };
        auto loadB = [&](int stage, int kc) {
            #pragma unroll
            for (int i = 0; i < 2; i++) {
                int e  = tid + 256 * i;
                int g  = e & 127;
                int k4 = e >> 7;
                int kk = kc * BK + k4 * 4;
                float4 v = *(const float4*)(W_ih + (size_t)(g0 + g) * IND + kk);
                sm.gemm.Bs[stage][k4 * 4 + 0][g] = v.x * wscale;
                sm.gemm.Bs[stage][k4 * 4 + 1][g] = v.y * wscale;
                sm.gemm.Bs[stage][k4 * 4 + 2][g] = v.z * wscale;
                sm.gemm.Bs[stage][k4 * 4 + 3][g] = v.w * wscale;
            }
        };

        loadA(0, 0); loadB(0, 0);
        __syncthreads();

        const int NKC = IND / BK;   // 12
        for (int kc = 0; kc < NKC; kc++) {
            int cur = kc & 1, nxt = cur ^ 1;
            if (kc + 1 < NKC) { loadA(nxt, kc + 1); loadB(nxt, kc + 1); }
            #pragma unroll
            for (int k = 0; k < BK; k++) {
                float a[8];
                *(float4*)&a[0] = *(const float4*)&sm.gemm.As[cur][k][ty * 8];
                *(float4*)&a[4] = *(const float4*)&sm.gemm.As[cur][k][ty * 8 + 4];
                unsigned long long bv[4];
                {
                    ulonglong2 b0 = *(const ulonglong2*)&sm.gemm.Bs[cur][k][tx * 8];
                    ulonglong2 b1 = *(const ulonglong2*)&sm.gemm.Bs[cur][k][tx * 8 + 4];
                    bv[0] = b0.x; bv[1] = b0.y; bv[2] = b1.x; bv[3] = b1.y;
                }
                #pragma unroll
                for (int i = 0; i < 8; i++) {
                    unsigned long long ad = dup2(a[i]);
                    fma2(acc[i][0], ad, bv[0]);
                    fma2(acc[i][1], ad, bv[1]);
                    fma2(acc[i][2], ad, bv[2]);
                    fma2(acc[i][3], ad, bv[3]);
                }
            }
            __syncthreads();
        }

        float bia[8];
        *(float4*)&bia[0] = *(const float4*)(b_ih + g0 + tx * 8);
        *(float4*)&bia[4] = *(const float4*)(b_ih + g0 + tx * 8 + 4);
        if (gblk < 2) {
            float bh[8];
            *(float4*)&bh[0] = *(const float4*)(b_hh + g0 + tx * 8);
            *(float4*)&bh[4] = *(const float4*)(b_hh + g0 + tx * 8 + 4);
            #pragma unroll
            for (int j = 0; j < 8; j++) bia[j] = (bia[j] + bh[j]) * 0.5f;
        }

        #pragma unroll
        for (int i = 0; i < 8; i++) {
            float c[8];
            unpk(acc[i][0], c[0], c[1]);
            unpk(acc[i][1], c[2], c[3]);
            unpk(acc[i][2], c[4], c[5]);
            unpk(acc[i][3], c[6], c[7]);
            #pragma unroll
            for (int j = 0; j < 8; j++) c[j] += bia[j];
            int bt = bt0 + ty * 8 + i;
            float* outp = gi + (size_t)bt * GG + g0 + tx * 8;
            *(float4*)(outp)     = *(float4*)&c[0];
            *(float4*)(outp + 4) = *(float4*)&c[4];
        }

        __threadfence();
        __syncthreads();
        if (tid == 0) atomicAdd(&g_cnt[b * NTBLK + tb], 1u);
        return;
    }

    // ================= scan role =================
    const int b = blockIdx.x;
    const int j = tid >> 1;     // state dim 0..127
    const int q = tid & 1;      // K-half 0..1

    float* dtbuf = sm.scan.dtbuf;
    float* zbA   = sm.scan.zbA;
    float* zbB   = sm.scan.zbB;

    // dt[t] = max(ts[t]-ts[t-1],0), dt[0]=0, dt[TT]=0
    {
        const float* tp = t_dyn + (size_t)b * TT;
        for (int i = tid; i < TT; i += 256) {
            float cur = __ldg(tp + i);
            float prv = (i > 0) ? __ldg(tp + i - 1) : cur;
            dtbuf[i] = fmaxf(cur - prv, 0.0f);
        }
        if (tid == 0) dtbuf[TT] = 0.0f;
    }

    // weights: rows {j, 128+j, 256+j}, K half [64q, 64q+64) -> 96 u64
    // Wr AND Wu prescaled by 0.5 (gate = 0.5 + 0.5*tanh(0.5*x))
    unsigned long long Wr[32], Wu[32], Wn[32];
    {
        const float4* wr = (const float4*)(W_hh + (size_t)j * DZC + 64 * q);
        const float4* wu = (const float4*)(W_hh + (size_t)(128 + j) * DZC + 64 * q);
        const float4* wn = (const float4*)(W_hh + (size_t)(256 + j) * DZC + 64 * q);
        #pragma unroll
        for (int i = 0; i < 16; i++) {
            float4 a = wr[i];
            Wr[2*i]   = pack2(a.x * 0.5f, a.y * 0.5f);
            Wr[2*i+1] = pack2(a.z * 0.5f, a.w * 0.5f);
            float4 c = wu[i];
            Wu[2*i]   = pack2(c.x * 0.5f, c.y * 0.5f);
            Wu[2*i+1] = pack2(c.z * 0.5f, c.w * 0.5f);
            float4 d = wn[i];
            Wn[2*i]   = pack2(d.x, d.y);
            Wn[2*i+1] = pack2(d.z, d.w);
        }
    }
    const float bh_n = (q == 0) ? b_hh[256 + j] : 0.0f;  // r/u bias folded in GEMM
    const int   L    = dyn_lens[b];                      // active steps (>=1)

    float lg  = log_gamma[j];
    float sp  = (lg > 20.0f) ? lg : log1pf(expf(lg));   // softplus
    const float gje = -1.4426950408889634f * sp;

    const unsigned int* cntp = &g_cnt[b * NTBLK];

    // padded z layout: dim k at index k + 16*(k>=64)
    const int wj = j + ((j >> 6) << 4);

    while (ldvol_(cntp) < 3u) { }
    __threadfence();

    // gi streams, distance-1 prefetch; pG/pN point at row t+1 at step t entry
    const float* pG = g_gi + (size_t)b * TT * GG + q * DZC + j;
    const float* pN = g_gi + (size_t)b * TT * GG + 2 * DZC + j;
    float gi_c = __ldg(pG);
    float gn_c = __ldg(pN);
    pG += GG; pN += GG;

    float* zp = Z_traj + (size_t)b * TT * DZC + j;   // row t at pair entry

    float zdj = z0[(size_t)b * DZC + j];
    float zlast = zdj;
    if (q == 0) zbA[wj] = zdj;

    // one active step; tn = t+1; offsets are call-site literals
    auto step = [&](int tn, int offG, int offZ, bool chk,
                    const float* __restrict__ zr, float* __restrict__ zw) {
        __syncthreads();   // z(t) visible; zw WAR-safe (double buffer)

        if (chk && (tn & (TBLK - 1)) == 0 && tn < L) {
            unsigned int need = (unsigned)(tn >> 7);
            while (ldvol_(cntp + need) < 3u) { }
            __threadfence();
        }
        // prefetch gi(tn)
        float giN = __ldg(pG + offG), gnN = __ldg(pN + offG);

        float edn = ex2f_(gje * dtbuf[tn]);   // decay t -> t+1

        // single-pass dot over K-half: 16 LDS.128, 96 fma2, reuse-ordered
        // (r,u,n consecutive on each z operand -> .reuse on shared src)
        const ulonglong2* zc = (const ulonglong2*)(zr + (q ? 80 : 0));
        unsigned long long ar0 = 0, ar1 = 0, au0 = 0, au1 = 0, an0 = 0, an1 = 0;
        ulonglong2 v0 = zc[0];
        ulonglong2 v1 = zc[1];
        #pragma unroll
        for (int i = 0; i < 16; i += 2) {
            ulonglong2 n0, n1;
            if (i + 2 < 16) { n0 = zc[i + 2]; n1 = zc[i + 3]; }
            fma2(ar0, Wr[2*i],   v0.x);
            fma2(au0, Wu[2*i],   v0.x);
            fma2(an0, Wn[2*i],   v0.x);
            fma2(ar0, Wr[2*i+1], v0.y);
            fma2(au0, Wu[2*i+1], v0.y);
            fma2(an0, Wn[2*i+1], v0.y);
            fma2(ar1, Wr[2*i+2], v1.x);
            fma2(au1, Wu[2*i+2], v1.x);
            fma2(an1, Wn[2*i+2], v1.x);
            fma2(ar1, Wr[2*i+3], v1.y);
            fma2(au1, Wu[2*i+3], v1.y);
            fma2(an1, Wn[2*i+3], v1.y);
            v0 = n0; v1 = n1;
        }
        add2(ar0, ar1); add2(au0, au1); add2(an0, an1);
        float x, y;
        unpk(ar0, x, y); float Sr = x + y;   // pre-scaled by 0.5
        unpk(au0, x, y); float Su = x + y;   // pre-scaled by 0.5
        if (q == 0) Sr += gi_c;              // gi r-row prescaled 0.5
        else        Su += gi_c;              // gi u-row prescaled 0.5
        // r/u reduces + MUFU issued first; latency overlaps Sn finish
        Sr += __shfl_xor_sync(0xffffffffu, Sr, 1);
        Su += __shfl_xor_sync(0xffffffffu, Su, 1);
        float rr = fmaf(tanhap_(Sr), 0.5f, 0.5f);
        float uu = fmaf(tanhap_(Su), 0.5f, 0.5f);

        unpk(an0, x, y); float Sn = x + y;
        if (q == 0) Sn += bh_n;
        Sn += __shfl_xor_sync(0xffffffffu, Sn, 1);

        // short tail: n-path only
        float nn = tanhap_(fmaf(rr, Sn, gn_c));
        float znew = nn + uu * (zdj - nn);
        float zd   = znew * edn;
        if (q == 0) zw[wj] = zd;            // critical exchange (q0 lane)
        else        *(zp + offZ) = znew;    // trajectory store (q1 lane)
        zdj   = zd;
        zlast = znew;

        gi_c = giN; gn_c = gnN;
    };

    int t = 0;
    while (t + 2 <= L) {
        step(t + 1, 0,  0,   false, zbA, zbB);
        step(t + 2, GG, DZC, true,  zbB, zbA);
        pG += 2 * GG; pN += 2 * GG; zp += 2 * DZC;
        t += 2;
    }
    if (t < L) {   // leftover odd step; parity: read zbA
        step(t + 1, 0, 0, false, zbA, zbB);
        t += 1;
    }

    // closed-form inactive tail: z_out(k) = z_{L-1} * exp(-gamma*(ts[k]-ts[L-1]))
    {
        const float* tsrc = t_dyn + (size_t)b * TT;
        float tl = __ldg(tsrc + (L - 1));
        float zl = zlast;
        if (q == 0) {
            float tend = __ldg(tsrc + (TT - 1));
            z_final[(size_t)b * DZC + j] = zl * ex2f_(gje * (tend - tl));
        }
        float* zob = Z_traj + (size_t)b * TT * DZC + j;
        for (int k = L + q; k < TT; k += 2) {
            float v = zl * ex2f_(gje * (__ldg(tsrc + k) - tl));
            zob[(size_t)k * DZC] = v;
        }
    }
}

// =====================================================================
// launch
// =====================================================================
extern "C" void kernel_launch(void* const* d_in, const int* in_sizes, int n_in,
                              void* d_out, int out_size)
{
    const float* z0        = (const float*)d_in[0];
    const float* t_dyn     = (const float*)d_in[1];
    const float* Y         = (const float*)d_in[2];
    const float* M         = (const float*)d_in[3];
    const int*   dyn_lens  = (const int*)  d_in[4];
    const float* H         = (const float*)d_in[5];
    const float* W_ih      = (const float*)d_in[6];
    const float* b_ih      = (const float*)d_in[7];
    const float* W_hh      = (const float*)d_in[8];
    const float* b_hh      = (const float*)d_in[9];
    const float* log_gamma = (const float*)d_in[10];

    float* out     = (float*)d_out;
    float* z_final = out;                       // (B, DZ)
    float* Z_traj  = out + (size_t)BB * DZC;    // (B, T, DZ)

    void* cnt_ptr = nullptr;
    cudaGetSymbolAddress(&cnt_ptr, g_cnt);
    cudaMemsetAsync(cnt_ptr, 0, sizeof(unsigned int) * BB * NTBLK);

    fused_kernel<<<SCAN_CTAS + GEMM_CTAS, 256>>>(
        z0, t_dyn, dyn_lens, Y, M, H, W_ih, b_ih, W_hh, b_hh, log_gamma,
        z_final, Z_traj);
}

// round 16
// speedup vs baseline: 2.2369x; 1.0271x over previous
#include <cuda_runtime.h>
#include <cuda_bf16.h>
#include <math.h>
#include <cstdint>

// Problem constants
#define BB   32
#define TT   4096
#define DZC  128
#define NDC  32
#define DHC  128
#define GG   384            // 3*DZ
#define IND  192            // 2*ND + DH

#define TBLK      128                 // timesteps per GEMM tile
#define NTBLK     (TT / TBLK)         // 32 t-blocks per batch
#define GEMM_CTAS (NTBLK * BB * 3)    // 3072
#define SCAN_CTAS BB                  // 32

// z exchange buffer: halves padded 16 floats apart -> bank-disjoint reads
#define ZPAD 144

// ---------------- scratch (no cudaMalloc allowed) ----------------
__device__ float        g_gi[(size_t)BB * TT * GG + 4 * GG];
__device__ unsigned int g_cnt[BB * NTBLK];

// ---------------- packed fp32x2 helpers (sm_100+) ----------------
__device__ __forceinline__ void fma2(unsigned long long& d,
                                     unsigned long long a,
                                     unsigned long long b) {
    asm("fma.rn.f32x2 %0, %1, %2, %0;" : "+l"(d) : "l"(a), "l"(b));
}
__device__ __forceinline__ void add2(unsigned long long& d, unsigned long long a) {
    asm("add.rn.f32x2 %0, %0, %1;" : "+l"(d) : "l"(a));
}
__device__ __forceinline__ unsigned long long dup2(float a) {
    unsigned long long r;
    asm("mov.b64 %0, {%1, %1};" : "=l"(r) : "f"(a));
    return r;
}
__device__ __forceinline__ unsigned long long pack2(float x, float y) {
    unsigned long long r;
    asm("mov.b64 %0, {%1, %2};" : "=l"(r) : "f"(x), "f"(y));
    return r;
}
__device__ __forceinline__ void unpk(unsigned long long v, float& x, float& y) {
    asm("mov.b64 {%0, %1}, %2;" : "=f"(x), "=f"(y) : "l"(v));
}
__device__ __forceinline__ float ex2f_(float x) {
    float y; asm("ex2.approx.f32 %0, %1;" : "=f"(y) : "f"(x)); return y;
}
__device__ __forceinline__ float tanhap_(float x) {
    float y; asm("tanh.approx.f32 %0, %1;" : "=f"(y) : "f"(x)); return y;
}
__device__ __forceinline__ unsigned int ldvol_(const unsigned int* p) {
    unsigned int v;
    asm volatile("ld.volatile.global.b32 %0, [%1];" : "=r"(v) : "l"(p));
    return v;
}

// =====================================================================
// Fused kernel. blockIdx.x < 32  -> scan role (one CTA per batch)
//               blockIdx.x >= 32 -> GEMM tile role (t-block-major order)
// GEMM adds b_ih; folds b_hh for r/u rows; r,u rows prescaled 0.5
// (gate = 0.5 + 0.5*tanh(0.5*x)).
// =====================================================================
#define Bb 128
#define BN 128
#define BK 16

struct ScanSmem {
    float dtbuf[TT + 4];
    float zbA[ZPAD];
    float zbB[ZPAD];
};
struct GemmSmem {
    float As[2][BK][Bb];
    float Bs[2][BK][BN];
};

__global__ __launch_bounds__(256, 1) void fused_kernel(
    const float* __restrict__ z0, const float* __restrict__ t_dyn,
    const int* __restrict__ dyn_lens,
    const float* __restrict__ Y, const float* __restrict__ M,
    const float* __restrict__ H,
    const float* __restrict__ W_ih, const float* __restrict__ b_ih,
    const float* __restrict__ W_hh, const float* __restrict__ b_hh,
    const float* __restrict__ log_gamma,
    float* __restrict__ z_final, float* __restrict__ Z_traj)
{
    __shared__ __align__(16) union { ScanSmem scan; GemmSmem gemm; } sm;

    const int tid = threadIdx.x;

    if (blockIdx.x >= SCAN_CTAS) {
        // ================= GEMM role =================
        const int gidx = blockIdx.x - SCAN_CTAS;
        const int tb   = gidx / (BB * 3);
        const int rem  = gidx % (BB * 3);
        const int b    = rem / 3;
        const int gblk = rem % 3;
        const int bt0  = b * TT + tb * TBLK;
        const int g0   = gblk * BN;
        const float wscale = (gblk < 2) ? 0.5f : 1.0f;

        float* gi = g_gi;
        const int tx = tid & 15;
        const int ty = tid >> 4;

        unsigned long long acc[8][4];
        #pragma unroll
        for (int i = 0; i < 8; i++)
            #pragma unroll
            for (int j = 0; j < 4; j++) acc[i][j] = 0ull;

        auto loadA = [&](int stage, int kc) {
            #pragma unroll
            for (int i = 0; i < 2; i++) {
                int e  = tid + 256 * i;
                int m  = e & 127;
                int k4 = e >> 7;
                int kk = kc * BK + k4 * 4;
                int bt = bt0 + m;
                float4 v;
                if (kk < 32)       v = *(const float4*)(Y + (size_t)bt * NDC + kk);
                else if (kk < 64)  v = *(const float4*)(M + (size_t)bt * NDC + (kk - 32));
                else               v = *(const float4*)(H + (size_t)bt * DHC + (kk - 64));
                sm.gemm.As[stage][k4 * 4 + 0][m] = v.x;
                sm.gemm.As[stage][k4 * 4 + 1][m] = v.y;
                sm.gemm.As[stage][k4 * 4 + 2][m] = v.z;
                sm.gemm.As[stage][k4 * 4 + 3][m] = v.w;
            }
        };
        auto loadB = [&](int stage, int kc) {
            #pragma unroll
            for (int i = 0; i < 2; i++) {
                int e  = tid + 256 * i;
                int g  = e & 127;
                int k4 = e >> 7;
                int kk = kc * BK + k4 * 4;
                float4 v = *(const float4*)(W_ih + (size_t)(g0 + g) * IND + kk);
                sm.gemm.Bs[stage][k4 * 4 + 0][g] = v.x * wscale;
                sm.gemm.Bs[stage][k4 * 4 + 1][g] = v.y * wscale;
                sm.gemm.Bs[stage][k4 * 4 + 2][g] = v.z * wscale;
                sm.gemm.Bs[stage][k4 * 4 + 3][g] = v.w * wscale;
            }
        };

        loadA(0, 0); loadB(0, 0);
        __syncthreads();

        const int NKC = IND / BK;   // 12
        for (int kc = 0; kc < NKC; kc++) {
            int cur = kc & 1, nxt = cur ^ 1;
            if (kc + 1 < NKC) { loadA(nxt, kc + 1); loadB(nxt, kc + 1); }
            #pragma unroll
            for (int k = 0; k < BK; k++) {
                float a[8];
                *(float4*)&a[0] = *(const float4*)&sm.gemm.As[cur][k][ty * 8];
                *(float4*)&a[4] = *(const float4*)&sm.gemm.As[cur][k][ty * 8 + 4];
                unsigned long long bv[4];
                {
                    ulonglong2 b0 = *(const ulonglong2*)&sm.gemm.Bs[cur][k][tx * 8];
                    ulonglong2 b1 = *(const ulonglong2*)&sm.gemm.Bs[cur][k][tx * 8 + 4];
                    bv[0] = b0.x; bv[1] = b0.y; bv[2] = b1.x; bv[3] = b1.y;
                }
                #pragma unroll
                for (int i = 0; i < 8; i++) {
                    unsigned long long ad = dup2(a[i]);
                    fma2(acc[i][0], ad, bv[0]);
                    fma2(acc[i][1], ad, bv[1]);
                    fma2(acc[i][2], ad, bv[2]);
                    fma2(acc[i][3], ad, bv[3]);
                }
            }
            __syncthreads();
        }

        float bia[8];
        *(float4*)&bia[0] = *(const float4*)(b_ih + g0 + tx * 8);
        *(float4*)&bia[4] = *(const float4*)(b_ih + g0 + tx * 8 + 4);
        if (gblk < 2) {
            float bh[8];
            *(float4*)&bh[0] = *(const float4*)(b_hh + g0 + tx * 8);
            *(float4*)&bh[4] = *(const float4*)(b_hh + g0 + tx * 8 + 4);
            #pragma unroll
            for (int j = 0; j < 8; j++) bia[j] = (bia[j] + bh[j]) * 0.5f;
        }

        #pragma unroll
        for (int i = 0; i < 8; i++) {
            float c[8];
            unpk(acc[i][0], c[0], c[1]);
            unpk(acc[i][1], c[2], c[3]);
            unpk(acc[i][2], c[4], c[5]);
            unpk(acc[i][3], c[6], c[7]);
            #pragma unroll
            for (int j = 0; j < 8; j++) c[j] += bia[j];
            int bt = bt0 + ty * 8 + i;
            float* outp = gi + (size_t)bt * GG + g0 + tx * 8;
            *(float4*)(outp)     = *(float4*)&c[0];
            *(float4*)(outp + 4) = *(float4*)&c[4];
        }

        __threadfence();
        __syncthreads();
        if (tid == 0) atomicAdd(&g_cnt[b * NTBLK + tb], 1u);
        return;
    }

    // ================= scan role =================
    const int b = blockIdx.x;
    const int j = tid >> 1;     // state dim 0..127
    const int q = tid & 1;      // K-half 0..1

    float* dtbuf = sm.scan.dtbuf;
    float* zbA   = sm.scan.zbA;
    float* zbB   = sm.scan.zbB;

    // dt[t] = max(ts[t]-ts[t-1],0), dt[0]=0, dt[TT..TT+3]=0
    {
        const float* tp = t_dyn + (size_t)b * TT;
        for (int i = tid; i < TT; i += 256) {
            float cur = __ldg(tp + i);
            float prv = (i > 0) ? __ldg(tp + i - 1) : cur;
            dtbuf[i] = fmaxf(cur - prv, 0.0f);
        }
        if (tid < 4) dtbuf[TT + tid] = 0.0f;
    }

    // weights: rows {j, 128+j, 256+j}, K half [64q, 64q+64) -> 96 u64
    // Wr, Wu prescaled 0.5 (gate = 0.5 + 0.5*tanh(0.5*x));
    // Wn ALSO prescaled 0.5: nn = tanh(gn + Sn' + T_r*Sn'), Sn' = 0.5*Sn_old.
    unsigned long long Wr[32], Wu[32], Wn[32];
    {
        const float4* wr = (const float4*)(W_hh + (size_t)j * DZC + 64 * q);
        const float4* wu = (const float4*)(W_hh + (size_t)(128 + j) * DZC + 64 * q);
        const float4* wn = (const float4*)(W_hh + (size_t)(256 + j) * DZC + 64 * q);
        #pragma unroll
        for (int i = 0; i < 16; i++) {
            float4 a = wr[i];
            Wr[2*i]   = pack2(a.x * 0.5f, a.y * 0.5f);
            Wr[2*i+1] = pack2(a.z * 0.5f, a.w * 0.5f);
            float4 c = wu[i];
            Wu[2*i]   = pack2(c.x * 0.5f, c.y * 0.5f);
            Wu[2*i+1] = pack2(c.z * 0.5f, c.w * 0.5f);
            float4 d = wn[i];
            Wn[2*i]   = pack2(d.x * 0.5f, d.y * 0.5f);
            Wn[2*i+1] = pack2(d.z * 0.5f, d.w * 0.5f);
        }
    }
    const float bh_n = (q == 0) ? (0.5f * b_hh[256 + j]) : 0.0f;  // prescaled
    const int   L    = dyn_lens[b];                               // active steps

    float lg  = log_gamma[j];
    float sp  = (lg > 20.0f) ? lg : log1pf(expf(lg));   // softplus
    const float gje = -1.4426950408889634f * sp;

    const unsigned int* cntp = &g_cnt[b * NTBLK];

    // padded z layout: dim k at index k + 16*(k>=64)
    const int wj = j + ((j >> 6) << 4);

    while (ldvol_(cntp) < 3u) { }
    __threadfence();

    // gi streams, distance-1 prefetch; pG/pN point at row t+1 at group entry
    const float* pG = g_gi + (size_t)b * TT * GG + q * DZC + j;
    const float* pN = g_gi + (size_t)b * TT * GG + 2 * DZC + j;
    float gi_c = __ldg(pG);
    float gn_c = __ldg(pN);
    pG += GG; pN += GG;

    float* zp = Z_traj + (size_t)b * TT * DZC + j;   // row t at group entry

    float zdj = z0[(size_t)b * DZC + j];
    float zlast = zdj;
    if (q == 0) zbA[wj] = zdj;

    // one active step; tn = t+1; offsets are call-site literals
    auto step = [&](int tn, int offG, int offZ, bool chk,
                    const float* __restrict__ zr, float* __restrict__ zw) {
        __syncthreads();   // z(t) visible; zw WAR-safe (double buffer)

        if (chk && (tn & (TBLK - 1)) == 0 && tn < L) {
            unsigned int need = (unsigned)(tn >> 7);
            while (ldvol_(cntp + need) < 3u) { }
            __threadfence();
        }
        // prefetch gi(tn)
        float giN = __ldg(pG + offG), gnN = __ldg(pN + offG);

        float edn = ex2f_(gje * dtbuf[tn]);   // decay t -> t+1

        // single-pass dot over K-half: 16 LDS.128, 96 fma2, reuse-ordered
        const ulonglong2* zc = (const ulonglong2*)(zr + (q ? 80 : 0));
        unsigned long long ar0 = 0, ar1 = 0, au0 = 0, au1 = 0, an0 = 0, an1 = 0;
        ulonglong2 v0 = zc[0];
        ulonglong2 v1 = zc[1];
        #pragma unroll
        for (int i = 0; i < 16; i += 2) {
            ulonglong2 n0, n1;
            if (i + 2 < 16) { n0 = zc[i + 2]; n1 = zc[i + 3]; }
            fma2(ar0, Wr[2*i],   v0.x);
            fma2(au0, Wu[2*i],   v0.x);
            fma2(an0, Wn[2*i],   v0.x);
            fma2(ar0, Wr[2*i+1], v0.y);
            fma2(au0, Wu[2*i+1], v0.y);
            fma2(an0, Wn[2*i+1], v0.y);
            fma2(ar1, Wr[2*i+2], v1.x);
            fma2(au1, Wu[2*i+2], v1.x);
            fma2(an1, Wn[2*i+2], v1.x);
            fma2(ar1, Wr[2*i+3], v1.y);
            fma2(au1, Wu[2*i+3], v1.y);
            fma2(an1, Wn[2*i+3], v1.y);
            v0 = n0; v1 = n1;
        }
        add2(ar0, ar1); add2(au0, au1); add2(an0, an1);
        float x, y;
        unpk(ar0, x, y); float Sr = x + y;   // pre-scaled by 0.5
        unpk(au0, x, y); float Su = x + y;   // pre-scaled by 0.5
        if (q == 0) Sr += gi_c;              // gi r-row prescaled 0.5
        else        Su += gi_c;              // gi u-row prescaled 0.5
        // r/u reduces + MUFU issued first; latency overlaps Sn finish
        Sr += __shfl_xor_sync(0xffffffffu, Sr, 1);
        Su += __shfl_xor_sync(0xffffffffu, Su, 1);
        float Tr = tanhap_(Sr);                           // raw tanh (r)
        float uu = fmaf(tanhap_(Su), 0.5f, 0.5f);

        unpk(an0, x, y); float Sn = x + y;   // = 0.5 * Sn_old
        if (q == 0) Sn += bh_n;              // bh_n prescaled 0.5
        Sn += __shfl_xor_sync(0xffffffffu, Sn, 1);
        float gs = gn_c + Sn;                // off the Tr chain

        // short tail: nn = tanh(gn + Sn' + Tr*Sn')
        float nn = tanhap_(fmaf(Tr, Sn, gs));
        float znew = nn + uu * (zdj - nn);
        float zd   = znew * edn;
        if (q == 0) zw[wj] = zd;            // critical exchange (q0 lane)
        else        *(zp + offZ) = znew;    // trajectory store (q1 lane)
        zdj   = zd;
        zlast = znew;

        gi_c = giN; gn_c = gnN;
    };

    int t = 0;
    while (t + 4 <= L) {
        step(t + 1, 0,      0,       false, zbA, zbB);
        step(t + 2, GG,     DZC,     false, zbB, zbA);
        step(t + 3, 2 * GG, 2 * DZC, false, zbA, zbB);
        step(t + 4, 3 * GG, 3 * DZC, true,  zbB, zbA);
        pG += 4 * GG; pN += 4 * GG; zp += 4 * DZC;
        t += 4;
    }
    // remainder (0..3 steps); buffer parity resumes at A
    if (t < L) {
        step(t + 1, 0, 0, false, zbA, zbB);
        t += 1;
        if (t < L) {
            step(t + 1, GG, DZC, false, zbB, zbA);
            t += 1;
            if (t < L) {
                step(t + 1, 2 * GG, 2 * DZC, false, zbA, zbB);
                t += 1;
            }
        }
    }

    // closed-form inactive tail: z_out(k) = z_{L-1} * exp(-gamma*(ts[k]-ts[L-1]))
    {
        const float* tsrc = t_dyn + (size_t)b * TT;
        float tl = __ldg(tsrc + (L - 1));
        float zl = zlast;
        if (q == 0) {
            float tend = __ldg(tsrc + (TT - 1));
            z_final[(size_t)b * DZC + j] = zl * ex2f_(gje * (tend - tl));
        }
        float* zob = Z_traj + (size_t)b * TT * DZC + j;
        for (int k = L + q; k < TT; k += 2) {
            float v = zl * ex2f_(gje * (__ldg(tsrc + k) - tl));
            zob[(size_t)k * DZC] = v;
        }
    }
}

// =====================================================================
// launch
// =====================================================================
extern "C" void kernel_launch(void* const* d_in, const int* in_sizes, int n_in,
                              void* d_out, int out_size)
{
    const float* z0        = (const float*)d_in[0];
    const float* t_dyn     = (const float*)d_in[1];
    const float* Y         = (const float*)d_in[2];
    const float* M         = (const float*)d_in[3];
    const int*   dyn_lens  = (const int*)  d_in[4];
    const float* H         = (const float*)d_in[5];
    const float* W_ih      = (const float*)d_in[6];
    const float* b_ih      = (const float*)d_in[7];
    const float* W_hh      = (const float*)d_in[8];
    const float* b_hh      = (const float*)d_in[9];
    const float* log_gamma = (const float*)d_in[10];

    float* out     = (float*)d_out;
    float* z_final = out;                       // (B, DZ)
    float* Z_traj  = out + (size_t)BB * DZC;    // (B, T, DZ)

    void* cnt_ptr = nullptr;
    cudaGetSymbolAddress(&cnt_ptr, g_cnt);
    cudaMemsetAsync(cnt_ptr, 0, sizeof(unsigned int) * BB * NTBLK);

    fused_kernel<<<SCAN_CTAS + GEMM_CTAS, 256>>>(
        z0, t_dyn, dyn_lens, Y, M, H, W_ih, b_ih, W_hh, b_hh, log_gamma,
        z_final, Z_traj);
}